// round 1
// baseline (speedup 1.0000x reference)
#include <cuda_runtime.h>
#include <cuda_bf16.h>
#include <math.h>

// ---------------- problem constants ----------------
#define Vv 32000
#define Dd 1024
#define NLAYER 4
#define ED 2048
#define Nn 16
#define DR 64
#define DCONV 4
#define Bb 2
#define Ll 1024
#define Mm (Bb * Ll)      // 2048 tokens
#define DX (DR + 2 * Nn)  // 96

// ---------------- scratch (no allocs allowed) ----------------
__device__ __align__(256) float g_x[Mm * Dd];
__device__ __align__(256) float g_xn[Mm * Dd];
__device__ __align__(256) float g_xz[Mm * 2 * ED];
__device__ __align__(256) float g_xs[Mm * ED];
__device__ __align__(256) float g_y[Mm * ED];
__device__ __align__(256) float g_delta[Mm * ED];
__device__ __align__(256) float g_dbc[Mm * DX];

// ---------------- embedding gather ----------------
__global__ void __launch_bounds__(256) embed_kernel(const int* __restrict__ tok,
                                                    const float* __restrict__ emb,
                                                    float* __restrict__ out) {
    int idx = blockIdx.x * 256 + threadIdx.x;   // over Mm*Dd
    int m = idx >> 10;
    int d = idx & 1023;
    out[idx] = emb[(size_t)tok[m] * Dd + d];
}

// ---------------- rmsnorm (block per row, D=1024) ----------------
__global__ void __launch_bounds__(256) rmsnorm_kernel(const float* __restrict__ x,
                                                      const float* __restrict__ w,
                                                      float* __restrict__ out) {
    int row = blockIdx.x;
    const float* xr = x + (size_t)row * Dd;
    float v[4];
    float s = 0.f;
#pragma unroll
    for (int i = 0; i < 4; i++) {
        v[i] = xr[threadIdx.x + i * 256];
        s += v[i] * v[i];
    }
#pragma unroll
    for (int o = 16; o; o >>= 1) s += __shfl_xor_sync(0xffffffffu, s, o);
    __shared__ float ss[8];
    if ((threadIdx.x & 31) == 0) ss[threadIdx.x >> 5] = s;
    __syncthreads();
    if (threadIdx.x < 32) {
        float t = (threadIdx.x < 8) ? ss[threadIdx.x] : 0.f;
#pragma unroll
        for (int o = 4; o; o >>= 1) t += __shfl_xor_sync(0xffffffffu, t, o);
        if (threadIdx.x == 0) ss[0] = t;
    }
    __syncthreads();
    float r = rsqrtf(ss[0] * (1.f / (float)Dd) + 1e-5f);
    float* orow = out + (size_t)row * Dd;
#pragma unroll
    for (int i = 0; i < 4; i++) {
        int d = threadIdx.x + i * 256;
        orow[d] = v[i] * r * w[d];
    }
}

// ---------------- depthwise causal conv (DC=4) + bias + silu ----------------
__global__ void __launch_bounds__(256) conv_silu_kernel(const float* __restrict__ xz,
                                                        const float* __restrict__ cw,
                                                        const float* __restrict__ cb,
                                                        float* __restrict__ xs) {
    int idx = blockIdx.x * 256 + threadIdx.x;    // over Mm*ED
    int e = idx & (ED - 1);
    int m = idx >> 11;          // token index b*L+l
    int l = m & (Ll - 1);
    const float* xin = xz + (size_t)m * (2 * ED) + e;   // xin part of xz
    float w0 = cw[e * 4 + 0], w1 = cw[e * 4 + 1], w2 = cw[e * 4 + 2], w3 = cw[e * 4 + 3];
    float acc = cb[e] + w3 * xin[0];
    if (l >= 1) acc += w2 * xin[-(2 * ED)];
    if (l >= 2) acc += w1 * xin[-2 * (2 * ED)];
    if (l >= 3) acc += w0 * xin[-3 * (2 * ED)];
    xs[idx] = acc / (1.f + __expf(-acc));       // silu
}

// ---------------- generic SGEMM: C(M,N) = A(M,K) * B(N,K)^T ----------------
// EPI: 0 = store, 1 = accumulate into C (residual), 2 = softplus(acc + bias[n])
#define BM 64
#define BN 64
#define BKT 16

template <int EPI>
__global__ void __launch_bounds__(256) sgemm_nt(const float* __restrict__ A, int lda,
                                                const float* __restrict__ Bm, int ldb,
                                                float* __restrict__ C, int ldc,
                                                int M, int N, int K,
                                                const float* __restrict__ bias) {
    __shared__ float As[BKT][BM];
    __shared__ float Bs[BKT][BN];
    int tid = threadIdx.x;
    int m0 = blockIdx.y * BM;
    int n0 = blockIdx.x * BN;
    int lrow = tid >> 2;
    int lkv = (tid & 3) << 2;
    int tx = tid & 15;     // n sub-tile
    int ty = tid >> 4;     // m sub-tile
    float acc[4][4] = {};

    for (int k0 = 0; k0 < K; k0 += BKT) {
        float4 av = make_float4(0.f, 0.f, 0.f, 0.f);
        if (m0 + lrow < M)
            av = *(const float4*)(A + (size_t)(m0 + lrow) * lda + k0 + lkv);
        As[lkv + 0][lrow] = av.x;
        As[lkv + 1][lrow] = av.y;
        As[lkv + 2][lrow] = av.z;
        As[lkv + 3][lrow] = av.w;
        float4 bv = make_float4(0.f, 0.f, 0.f, 0.f);
        if (n0 + lrow < N)
            bv = *(const float4*)(Bm + (size_t)(n0 + lrow) * ldb + k0 + lkv);
        Bs[lkv + 0][lrow] = bv.x;
        Bs[lkv + 1][lrow] = bv.y;
        Bs[lkv + 2][lrow] = bv.z;
        Bs[lkv + 3][lrow] = bv.w;
        __syncthreads();
#pragma unroll
        for (int k = 0; k < BKT; k++) {
            float a[4], b[4];
#pragma unroll
            for (int i = 0; i < 4; i++) a[i] = As[k][ty * 4 + i];
#pragma unroll
            for (int j = 0; j < 4; j++) b[j] = Bs[k][tx * 4 + j];
#pragma unroll
            for (int i = 0; i < 4; i++)
#pragma unroll
                for (int j = 0; j < 4; j++) acc[i][j] = fmaf(a[i], b[j], acc[i][j]);
        }
        __syncthreads();
    }

#pragma unroll
    for (int i = 0; i < 4; i++) {
        int m = m0 + ty * 4 + i;
        if (m >= M) continue;
#pragma unroll
        for (int j = 0; j < 4; j++) {
            int n = n0 + tx * 4 + j;
            if (n >= N) continue;
            float v = acc[i][j];
            size_t off = (size_t)m * ldc + n;
            if (EPI == 1) v += C[off];
            if (EPI == 2) {
                v += bias[n];
                v = (v > 20.f) ? v : log1pf(expf(v));   // softplus
            }
            C[off] = v;
        }
    }
}

// ---------------- selective scan ----------------
// 16 lanes per channel (one state n each), h kept in register, serial over t.
// Fuses: dA/dBx on the fly, y = sum_n h*C + D*xs, gate by silu(z), write y.
__global__ void __launch_bounds__(256) scan_kernel(const float* __restrict__ delta,
                                                   const float* __restrict__ xs,
                                                   const float* __restrict__ dbc,
                                                   const float* __restrict__ xz,
                                                   const float* __restrict__ A_log,
                                                   const float* __restrict__ Dp,
                                                   float* __restrict__ y) {
    int ch = blockIdx.x * 16 + (threadIdx.x >> 4);   // 0 .. B*ED-1
    int n = threadIdx.x & 15;
    int b = ch >> 11;          // / ED
    int e = ch & (ED - 1);
    // A = -exp(A_log);  premultiply by log2(e) so dA = exp2f(delta * a2)
    float a2 = -__expf(A_log[e * Nn + n]) * 1.44269504f;
    float dpar = Dp[e];
    float h = 0.f;
    size_t m0 = (size_t)b * Ll;
    const float* pd = delta + m0 * ED + e;
    const float* pxs = xs + m0 * ED + e;
    const float* pB = dbc + m0 * DX + DR + n;
    const float* pC = dbc + m0 * DX + DR + Nn + n;
    const float* pz = xz + m0 * (2 * ED) + ED + e;
    float* py = y + m0 * ED + e;

    for (int t = 0; t < Ll; t++) {
        float d = *pd;
        float xv = *pxs;
        float Bn = *pB;
        float Cn = *pC;
        float da = exp2f(d * a2);
        h = fmaf(da, h, d * xv * Bn);
        float p = h * Cn;
        p += __shfl_xor_sync(0xffffffffu, p, 1);
        p += __shfl_xor_sync(0xffffffffu, p, 2);
        p += __shfl_xor_sync(0xffffffffu, p, 4);
        p += __shfl_xor_sync(0xffffffffu, p, 8);
        if (n == 0) {
            float z = *pz;
            float sz = z / (1.f + __expf(-z));
            py[0] = (p + dpar * xv) * sz;
        }
        pd += ED;
        pxs += ED;
        pB += DX;
        pC += DX;
        pz += 2 * ED;
        py += ED;
    }
}

// ---------------- host side ----------------
static void launch_sgemm(int epi, const float* A, int lda, const float* B, int ldb,
                         float* C, int ldc, int M, int N, int K, const float* bias) {
    dim3 grid((N + BN - 1) / BN, (M + BM - 1) / BM);
    dim3 block(256);
    if (epi == 0)
        sgemm_nt<0><<<grid, block>>>(A, lda, B, ldb, C, ldc, M, N, K, bias);
    else if (epi == 1)
        sgemm_nt<1><<<grid, block>>>(A, lda, B, ldb, C, ldc, M, N, K, bias);
    else
        sgemm_nt<2><<<grid, block>>>(A, lda, B, ldb, C, ldc, M, N, K, bias);
}

extern "C" void kernel_launch(void* const* d_in, const int* in_sizes, int n_in,
                              void* d_out, int out_size) {
    const int* tokens = (const int*)d_in[0];
    const float* embedding = (const float*)d_in[1];
    const float* in_proj_w = (const float*)d_in[2];
    const float* conv_w = (const float*)d_in[3];
    const float* conv_b = (const float*)d_in[4];
    const float* x_proj_w = (const float*)d_in[5];
    const float* dt_proj_w = (const float*)d_in[6];
    const float* dt_proj_b = (const float*)d_in[7];
    const float* A_log = (const float*)d_in[8];
    const float* D_param = (const float*)d_in[9];
    const float* out_proj_w = (const float*)d_in[10];
    const float* norm_w = (const float*)d_in[11];
    const float* norm_f_w = (const float*)d_in[12];
    float* logits = (float*)d_out;

    float *px, *pxn, *pxz, *pxs, *py, *pdelta, *pdbc;
    cudaGetSymbolAddress((void**)&px, g_x);
    cudaGetSymbolAddress((void**)&pxn, g_xn);
    cudaGetSymbolAddress((void**)&pxz, g_xz);
    cudaGetSymbolAddress((void**)&pxs, g_xs);
    cudaGetSymbolAddress((void**)&py, g_y);
    cudaGetSymbolAddress((void**)&pdelta, g_delta);
    cudaGetSymbolAddress((void**)&pdbc, g_dbc);

    // x = embedding[tokens]
    embed_kernel<<<(Mm * Dd) / 256, 256>>>(tokens, embedding, px);

    for (int l = 0; l < NLAYER; l++) {
        // xn = rmsnorm(x, norm_w[l])
        rmsnorm_kernel<<<Mm, 256>>>(px, norm_w + (size_t)l * Dd, pxn);
        // xz = xn @ in_proj_w[l].T     (M, 2*ED)
        launch_sgemm(0, pxn, Dd, in_proj_w + (size_t)l * 2 * ED * Dd, Dd,
                     pxz, 2 * ED, Mm, 2 * ED, Dd, nullptr);
        // xs = silu(conv(xin) + cb)
        conv_silu_kernel<<<(Mm * ED) / 256, 256>>>(pxz, conv_w + (size_t)l * ED * DCONV,
                                                   conv_b + (size_t)l * ED, pxs);
        // dbc = xs @ x_proj_w[l].T     (M, 96)
        launch_sgemm(0, pxs, ED, x_proj_w + (size_t)l * DX * ED, ED,
                     pdbc, DX, Mm, DX, ED, nullptr);
        // delta = softplus(delta_r @ dt_proj_w[l].T + dtb)   (M, ED)
        launch_sgemm(2, pdbc, DX, dt_proj_w + (size_t)l * ED * DR, DR,
                     pdelta, ED, Mm, ED, DR, dt_proj_b + (size_t)l * ED);
        // selective scan -> y (gated, +D*xs)
        scan_kernel<<<(Bb * ED) / 16, 256>>>(pdelta, pxs, pdbc, pxz,
                                             A_log + (size_t)l * ED * Nn,
                                             D_param + (size_t)l * ED, py);
        // x += y @ out_proj_w[l].T   (residual fused in epilogue)
        launch_sgemm(1, py, ED, out_proj_w + (size_t)l * Dd * ED, ED,
                     px, Dd, Mm, Dd, ED, nullptr);
    }

    // final norm + logits = xn @ embedding.T
    rmsnorm_kernel<<<Mm, 256>>>(px, norm_f_w, pxn);
    launch_sgemm(0, pxn, Dd, embedding, Dd, logits, Vv, Mm, Vv, Dd, nullptr);
}

// round 2
// speedup vs baseline: 1.0052x; 1.0052x over previous
#include <cuda_runtime.h>
#include <cuda_bf16.h>
#include <math.h>

// ---------------- problem constants ----------------
#define Vv 32000
#define Dd 1024
#define NLAYER 4
#define ED 2048
#define Nn 16
#define DR 64
#define DCONV 4
#define Bb 2
#define Ll 1024
#define Mm (Bb * Ll)      // 2048 tokens
#define DX (DR + 2 * Nn)  // 96

// ---------------- scratch (no allocs allowed) ----------------
__device__ __align__(256) float g_x[Mm * Dd];
__device__ __align__(256) float g_xn[Mm * Dd];
__device__ __align__(256) float g_xz[Mm * 2 * ED];
__device__ __align__(256) float g_xs[Mm * ED];
__device__ __align__(256) float g_y[Mm * ED];
__device__ __align__(256) float g_delta[Mm * ED];
__device__ __align__(256) float g_dbc[Mm * DX];

// ---------------- embedding gather ----------------
__global__ void __launch_bounds__(256) embed_kernel(const int* __restrict__ tok,
                                                    const float* __restrict__ emb,
                                                    float* __restrict__ out) {
    int idx = blockIdx.x * 256 + threadIdx.x;   // over Mm*Dd
    int m = idx >> 10;
    int d = idx & 1023;
    out[idx] = emb[(size_t)tok[m] * Dd + d];
}

// ---------------- rmsnorm (block per row, D=1024) ----------------
__global__ void __launch_bounds__(256) rmsnorm_kernel(const float* __restrict__ x,
                                                      const float* __restrict__ w,
                                                      float* __restrict__ out) {
    int row = blockIdx.x;
    const float* xr = x + (size_t)row * Dd;
    float v[4];
    float s = 0.f;
#pragma unroll
    for (int i = 0; i < 4; i++) {
        v[i] = xr[threadIdx.x + i * 256];
        s += v[i] * v[i];
    }
#pragma unroll
    for (int o = 16; o; o >>= 1) s += __shfl_xor_sync(0xffffffffu, s, o);
    __shared__ float ss[8];
    if ((threadIdx.x & 31) == 0) ss[threadIdx.x >> 5] = s;
    __syncthreads();
    if (threadIdx.x < 32) {
        float t = (threadIdx.x < 8) ? ss[threadIdx.x] : 0.f;
#pragma unroll
        for (int o = 4; o; o >>= 1) t += __shfl_xor_sync(0xffffffffu, t, o);
        if (threadIdx.x == 0) ss[0] = t;
    }
    __syncthreads();
    float r = rsqrtf(ss[0] * (1.f / (float)Dd) + 1e-5f);
    float* orow = out + (size_t)row * Dd;
#pragma unroll
    for (int i = 0; i < 4; i++) {
        int d = threadIdx.x + i * 256;
        orow[d] = v[i] * r * w[d];
    }
}

// ---------------- depthwise causal conv (DC=4) + bias + silu ----------------
__global__ void __launch_bounds__(256) conv_silu_kernel(const float* __restrict__ xz,
                                                        const float* __restrict__ cw,
                                                        const float* __restrict__ cb,
                                                        float* __restrict__ xs) {
    int idx = blockIdx.x * 256 + threadIdx.x;    // over Mm*ED
    int e = idx & (ED - 1);
    int m = idx >> 11;          // token index b*L+l
    int l = m & (Ll - 1);
    const float* xin = xz + (size_t)m * (2 * ED) + e;   // xin part of xz
    float w0 = cw[e * 4 + 0], w1 = cw[e * 4 + 1], w2 = cw[e * 4 + 2], w3 = cw[e * 4 + 3];
    float acc = cb[e] + w3 * xin[0];
    if (l >= 1) acc += w2 * xin[-(2 * ED)];
    if (l >= 2) acc += w1 * xin[-2 * (2 * ED)];
    if (l >= 3) acc += w0 * xin[-3 * (2 * ED)];
    xs[idx] = acc / (1.f + __expf(-acc));       // silu
}

// ---------------- generic SGEMM: C(M,N) = A(M,K) * B(N,K)^T ----------------
// EPI: 0 = store, 1 = accumulate into C (residual), 2 = softplus(acc + bias[n])
#define BM 64
#define BN 64
#define BKT 16

template <int EPI>
__global__ void __launch_bounds__(256) sgemm_nt(const float* __restrict__ A, int lda,
                                                const float* __restrict__ Bm, int ldb,
                                                float* __restrict__ C, int ldc,
                                                int M, int N, int K,
                                                const float* __restrict__ bias) {
    __shared__ float As[BKT][BM];
    __shared__ float Bs[BKT][BN];
    int tid = threadIdx.x;
    int m0 = blockIdx.y * BM;
    int n0 = blockIdx.x * BN;
    int lrow = tid >> 2;
    int lkv = (tid & 3) << 2;
    int tx = tid & 15;     // n sub-tile
    int ty = tid >> 4;     // m sub-tile
    float acc[4][4] = {};

    for (int k0 = 0; k0 < K; k0 += BKT) {
        float4 av = make_float4(0.f, 0.f, 0.f, 0.f);
        if (m0 + lrow < M)
            av = *(const float4*)(A + (size_t)(m0 + lrow) * lda + k0 + lkv);
        As[lkv + 0][lrow] = av.x;
        As[lkv + 1][lrow] = av.y;
        As[lkv + 2][lrow] = av.z;
        As[lkv + 3][lrow] = av.w;
        float4 bv = make_float4(0.f, 0.f, 0.f, 0.f);
        if (n0 + lrow < N)
            bv = *(const float4*)(Bm + (size_t)(n0 + lrow) * ldb + k0 + lkv);
        Bs[lkv + 0][lrow] = bv.x;
        Bs[lkv + 1][lrow] = bv.y;
        Bs[lkv + 2][lrow] = bv.z;
        Bs[lkv + 3][lrow] = bv.w;
        __syncthreads();
#pragma unroll
        for (int k = 0; k < BKT; k++) {
            float a[4], b[4];
#pragma unroll
            for (int i = 0; i < 4; i++) a[i] = As[k][ty * 4 + i];
#pragma unroll
            for (int j = 0; j < 4; j++) b[j] = Bs[k][tx * 4 + j];
#pragma unroll
            for (int i = 0; i < 4; i++)
#pragma unroll
                for (int j = 0; j < 4; j++) acc[i][j] = fmaf(a[i], b[j], acc[i][j]);
        }
        __syncthreads();
    }

#pragma unroll
    for (int i = 0; i < 4; i++) {
        int m = m0 + ty * 4 + i;
        if (m >= M) continue;
#pragma unroll
        for (int j = 0; j < 4; j++) {
            int n = n0 + tx * 4 + j;
            if (n >= N) continue;
            float v = acc[i][j];
            size_t off = (size_t)m * ldc + n;
            if (EPI == 1) v += C[off];
            if (EPI == 2) {
                v += bias[n];
                v = (v > 20.f) ? v : log1pf(expf(v));   // softplus
            }
            C[off] = v;
        }
    }
}

// ---------------- selective scan ----------------
// 16 lanes per channel (one state n each), h kept in register, serial over t.
// Fuses: dA/dBx on the fly, y = sum_n h*C + D*xs, gate by silu(z), write y.
__global__ void __launch_bounds__(256) scan_kernel(const float* __restrict__ delta,
                                                   const float* __restrict__ xs,
                                                   const float* __restrict__ dbc,
                                                   const float* __restrict__ xz,
                                                   const float* __restrict__ A_log,
                                                   const float* __restrict__ Dp,
                                                   float* __restrict__ y) {
    int ch = blockIdx.x * 16 + (threadIdx.x >> 4);   // 0 .. B*ED-1
    int n = threadIdx.x & 15;
    int b = ch >> 11;          // / ED
    int e = ch & (ED - 1);
    // A = -exp(A_log);  premultiply by log2(e) so dA = exp2f(delta * a2)
    float a2 = -__expf(A_log[e * Nn + n]) * 1.44269504f;
    float dpar = Dp[e];
    float h = 0.f;
    size_t m0 = (size_t)b * Ll;
    const float* pd = delta + m0 * ED + e;
    const float* pxs = xs + m0 * ED + e;
    const float* pB = dbc + m0 * DX + DR + n;
    const float* pC = dbc + m0 * DX + DR + Nn + n;
    const float* pz = xz + m0 * (2 * ED) + ED + e;
    float* py = y + m0 * ED + e;

    for (int t = 0; t < Ll; t++) {
        float d = *pd;
        float xv = *pxs;
        float Bn = *pB;
        float Cn = *pC;
        float da = exp2f(d * a2);
        h = fmaf(da, h, d * xv * Bn);
        float p = h * Cn;
        p += __shfl_xor_sync(0xffffffffu, p, 1);
        p += __shfl_xor_sync(0xffffffffu, p, 2);
        p += __shfl_xor_sync(0xffffffffu, p, 4);
        p += __shfl_xor_sync(0xffffffffu, p, 8);
        if (n == 0) {
            float z = *pz;
            float sz = z / (1.f + __expf(-z));
            py[0] = (p + dpar * xv) * sz;
        }
        pd += ED;
        pxs += ED;
        pB += DX;
        pC += DX;
        pz += 2 * ED;
        py += ED;
    }
}

// ---------------- host side ----------------
static void launch_sgemm(int epi, const float* A, int lda, const float* B, int ldb,
                         float* C, int ldc, int M, int N, int K, const float* bias) {
    dim3 grid((N + BN - 1) / BN, (M + BM - 1) / BM);
    dim3 block(256);
    if (epi == 0)
        sgemm_nt<0><<<grid, block>>>(A, lda, B, ldb, C, ldc, M, N, K, bias);
    else if (epi == 1)
        sgemm_nt<1><<<grid, block>>>(A, lda, B, ldb, C, ldc, M, N, K, bias);
    else
        sgemm_nt<2><<<grid, block>>>(A, lda, B, ldb, C, ldc, M, N, K, bias);
}

extern "C" void kernel_launch(void* const* d_in, const int* in_sizes, int n_in,
                              void* d_out, int out_size) {
    const int* tokens = (const int*)d_in[0];
    const float* embedding = (const float*)d_in[1];
    const float* in_proj_w = (const float*)d_in[2];
    const float* conv_w = (const float*)d_in[3];
    const float* conv_b = (const float*)d_in[4];
    const float* x_proj_w = (const float*)d_in[5];
    const float* dt_proj_w = (const float*)d_in[6];
    const float* dt_proj_b = (const float*)d_in[7];
    const float* A_log = (const float*)d_in[8];
    const float* D_param = (const float*)d_in[9];
    const float* out_proj_w = (const float*)d_in[10];
    const float* norm_w = (const float*)d_in[11];
    const float* norm_f_w = (const float*)d_in[12];
    float* logits = (float*)d_out;

    float *px, *pxn, *pxz, *pxs, *py, *pdelta, *pdbc;
    cudaGetSymbolAddress((void**)&px, g_x);
    cudaGetSymbolAddress((void**)&pxn, g_xn);
    cudaGetSymbolAddress((void**)&pxz, g_xz);
    cudaGetSymbolAddress((void**)&pxs, g_xs);
    cudaGetSymbolAddress((void**)&py, g_y);
    cudaGetSymbolAddress((void**)&pdelta, g_delta);
    cudaGetSymbolAddress((void**)&pdbc, g_dbc);

    // x = embedding[tokens]
    embed_kernel<<<(Mm * Dd) / 256, 256>>>(tokens, embedding, px);

    for (int l = 0; l < NLAYER; l++) {
        // xn = rmsnorm(x, norm_w[l])
        rmsnorm_kernel<<<Mm, 256>>>(px, norm_w + (size_t)l * Dd, pxn);
        // xz = xn @ in_proj_w[l].T     (M, 2*ED)
        launch_sgemm(0, pxn, Dd, in_proj_w + (size_t)l * 2 * ED * Dd, Dd,
                     pxz, 2 * ED, Mm, 2 * ED, Dd, nullptr);
        // xs = silu(conv(xin) + cb)
        conv_silu_kernel<<<(Mm * ED) / 256, 256>>>(pxz, conv_w + (size_t)l * ED * DCONV,
                                                   conv_b + (size_t)l * ED, pxs);
        // dbc = xs @ x_proj_w[l].T     (M, 96)
        launch_sgemm(0, pxs, ED, x_proj_w + (size_t)l * DX * ED, ED,
                     pdbc, DX, Mm, DX, ED, nullptr);
        // delta = softplus(delta_r @ dt_proj_w[l].T + dtb)   (M, ED)
        launch_sgemm(2, pdbc, DX, dt_proj_w + (size_t)l * ED * DR, DR,
                     pdelta, ED, Mm, ED, DR, dt_proj_b + (size_t)l * ED);
        // selective scan -> y (gated, +D*xs)
        scan_kernel<<<(Bb * ED) / 16, 256>>>(pdelta, pxs, pdbc, pxz,
                                             A_log + (size_t)l * ED * Nn,
                                             D_param + (size_t)l * ED, py);
        // x += y @ out_proj_w[l].T   (residual fused in epilogue)
        launch_sgemm(1, py, ED, out_proj_w + (size_t)l * Dd * ED, ED,
                     px, Dd, Mm, Dd, ED, nullptr);
    }

    // final norm + logits = xn @ embedding.T
    rmsnorm_kernel<<<Mm, 256>>>(px, norm_f_w, pxn);
    launch_sgemm(0, pxn, Dd, embedding, Dd, logits, Vv, Mm, Vv, Dd, nullptr);
}